// round 2
// baseline (speedup 1.0000x reference)
#include <cuda_runtime.h>
#include <cuda_bf16.h>

#define NN 100000
#define NG 64

// ---------------- scratch (device globals; no allocation allowed) ----------
__device__ float g_dinv[NN];
__device__ float g_h1  [(size_t)NN * 128];
__device__ float g_agg1[(size_t)NN * 128];
__device__ float g_h2  [(size_t)NN * 64];
__device__ float g_agg2[(size_t)NN * 64];
__device__ float g_gsum[NG * 64];
__device__ float g_gcnt[NG];

// ---------------- init: deg accumulator = 1 (self loop), zero pool bufs ----
__global__ void k_init(int n) {
    int i = blockIdx.x * blockDim.x + threadIdx.x;
    if (i < n)       g_dinv[i] = 1.0f;
    if (i < NG * 64) g_gsum[i] = 0.0f;
    if (i < NG)      g_gcnt[i] = 0.0f;
}

// ---------------- degree over dst -----------------------------------------
__global__ void k_deg(const int* __restrict__ dst, int E) {
    int e = blockIdx.x * blockDim.x + threadIdx.x;
    if (e < E) atomicAdd(&g_dinv[dst[e]], 1.0f);
}

__global__ void k_rsqrt(int n) {
    int i = blockIdx.x * blockDim.x + threadIdx.x;
    if (i < n) g_dinv[i] = rsqrtf(g_dinv[i]);
}

// ---------------- tiled fp32 GEMM: C[M,N] = A[M,K] @ B[K,N] ----------------
// LAYER 1: A = x (param), C = g_h1, N=128. LAYER 2: A = g_h1, C = g_h2, N=64.
template <int LAYER>
__global__ void k_gemm(const float* __restrict__ Ain,
                       const float* __restrict__ B, int M) {
    constexpr int N = (LAYER == 1) ? 128 : 64;
    constexpr int K = 128;
    const float* __restrict__ A = (LAYER == 1) ? Ain : g_h1;
    float* __restrict__       C = (LAYER == 1) ? g_h1 : g_h2;

    __shared__ float As[16][64];   // [k][m] (transposed)
    __shared__ float Bs[16][64];   // [k][n]

    const int tid = threadIdx.x;          // 256 threads
    const int tx  = tid & 15;             // 0..15  -> 4 cols each
    const int ty  = tid >> 4;             // 0..15  -> 4 rows each
    const int mbase = blockIdx.y * 64;
    const int nbase = blockIdx.x * 64;

    const int ar = tid >> 2;              // 0..63 tile row
    const int ak = (tid & 3) << 2;        // 0,4,8,12
    const int br = tid >> 4;              // 0..15 tile k-row
    const int bn = (tid & 15) << 2;       // 0..60

    float acc[4][4];
#pragma unroll
    for (int i = 0; i < 4; i++)
#pragma unroll
        for (int j = 0; j < 4; j++) acc[i][j] = 0.0f;

    for (int k0 = 0; k0 < K; k0 += 16) {
        float4 av = make_float4(0.f, 0.f, 0.f, 0.f);
        if (mbase + ar < M)
            av = *reinterpret_cast<const float4*>(
                A + (size_t)(mbase + ar) * K + k0 + ak);
        As[ak + 0][ar] = av.x;
        As[ak + 1][ar] = av.y;
        As[ak + 2][ar] = av.z;
        As[ak + 3][ar] = av.w;

        float4 bv = *reinterpret_cast<const float4*>(
            B + (size_t)(k0 + br) * N + nbase + bn);
        *reinterpret_cast<float4*>(&Bs[br][bn]) = bv;

        __syncthreads();
#pragma unroll
        for (int kk = 0; kk < 16; kk++) {
            float a0 = As[kk][ty * 4 + 0];
            float a1 = As[kk][ty * 4 + 1];
            float a2 = As[kk][ty * 4 + 2];
            float a3 = As[kk][ty * 4 + 3];
            float b0 = Bs[kk][tx * 4 + 0];
            float b1 = Bs[kk][tx * 4 + 1];
            float b2 = Bs[kk][tx * 4 + 2];
            float b3 = Bs[kk][tx * 4 + 3];
            acc[0][0] += a0 * b0; acc[0][1] += a0 * b1; acc[0][2] += a0 * b2; acc[0][3] += a0 * b3;
            acc[1][0] += a1 * b0; acc[1][1] += a1 * b1; acc[1][2] += a1 * b2; acc[1][3] += a1 * b3;
            acc[2][0] += a2 * b0; acc[2][1] += a2 * b1; acc[2][2] += a2 * b2; acc[2][3] += a2 * b3;
            acc[3][0] += a3 * b0; acc[3][1] += a3 * b1; acc[3][2] += a3 * b2; acc[3][3] += a3 * b3;
        }
        __syncthreads();
    }

#pragma unroll
    for (int i = 0; i < 4; i++) {
        int m = mbase + ty * 4 + i;
        if (m < M) {
            float4 v = make_float4(acc[i][0], acc[i][1], acc[i][2], acc[i][3]);
            *reinterpret_cast<float4*>(C + (size_t)m * N + nbase + tx * 4) = v;
        }
    }
}

// ---------------- self-loop term: agg = dinv^2 * h -------------------------
template <int LAYER>
__global__ void k_self(int n) {
    constexpr int D = (LAYER == 1) ? 128 : 64;
    const float* __restrict__ h   = (LAYER == 1) ? g_h1 : g_h2;
    float* __restrict__       agg = (LAYER == 1) ? g_agg1 : g_agg2;
    int i = blockIdx.x * blockDim.x + threadIdx.x;
    if (i < n) {
        float di = g_dinv[i / D];
        agg[i] = di * di * h[i];
    }
}

// ---------------- edge scatter: agg[dst] += dinv[s]*dinv[d] * h[src] -------
template <int LAYER>
__global__ void k_edge(const int* __restrict__ src,
                       const int* __restrict__ dst, int E) {
    constexpr int D = (LAYER == 1) ? 128 : 64;
    const float* __restrict__ h   = (LAYER == 1) ? g_h1 : g_h2;
    float* __restrict__       agg = (LAYER == 1) ? g_agg1 : g_agg2;

    int w = (blockIdx.x * blockDim.x + threadIdx.x) >> 5;  // warp per edge
    if (w >= E) return;
    int lane = threadIdx.x & 31;
    int s = __ldg(src + w);
    int d = __ldg(dst + w);
    float nw = g_dinv[s] * g_dinv[d];
    const float* hs = h + (size_t)s * D;
    float*       ad = agg + (size_t)d * D;
#pragma unroll
    for (int j = 0; j < D / 32; j++) {
        int f = lane + 32 * j;
        atomicAdd(ad + f, nw * __ldg(hs + f));
    }
}

// ---------------- layer-1 bias + relu (into g_h1 for reuse) ----------------
__global__ void k_brelu1(const float* __restrict__ b1, int n) {
    int i = blockIdx.x * blockDim.x + threadIdx.x;
    if (i < n) g_h1[i] = fmaxf(g_agg1[i] + __ldg(b1 + (i & 127)), 0.0f);
}

// ---------------- per-graph node counts ------------------------------------
__global__ void k_cnt(const int* __restrict__ batch, int n) {
    int i = blockIdx.x * blockDim.x + threadIdx.x;
    if (i < n) atomicAdd(&g_gcnt[batch[i]], 1.0f);
}

// ---------------- layer-2 bias + relu + pooled sums ------------------------
__global__ void k_pool(const int* __restrict__ batch,
                       const float* __restrict__ b2, int n) {
    int i = blockIdx.x * blockDim.x + threadIdx.x;
    if (i < n) {
        int node = i >> 6;
        int f    = i & 63;
        float v = fmaxf(g_agg2[i] + __ldg(b2 + f), 0.0f);
        int g = __ldg(batch + node);
        atomicAdd(&g_gsum[(g << 6) + f], v);
    }
}

// ---------------- mean -----------------------------------------------------
__global__ void k_final(float* __restrict__ out) {
    int i = blockIdx.x * blockDim.x + threadIdx.x;
    if (i < NG * 64) out[i] = g_gsum[i] / fmaxf(g_gcnt[i >> 6], 1.0f);
}

// ===========================================================================
extern "C" void kernel_launch(void* const* d_in, const int* in_sizes, int n_in,
                              void* d_out, int out_size) {
    const float* x     = (const float*)d_in[0];
    const int*   ei    = (const int*)d_in[1];
    const int*   batch = (const int*)d_in[2];
    const float* W1    = (const float*)d_in[3];
    const float* b1    = (const float*)d_in[4];
    const float* W2    = (const float*)d_in[5];
    const float* b2    = (const float*)d_in[6];
    float*       out   = (float*)d_out;

    const int N = in_sizes[2];        // 100000 nodes
    const int E = in_sizes[1] / 2;    // 1600000 edges
    const int* src = ei;
    const int* dst = ei + E;

    const int TB = 256;
    int nb_N    = (N + TB - 1) / TB;
    int nb_E    = (E + TB - 1) / TB;
    int nb_ND1  = (N * 128 + TB - 1) / TB;
    int nb_ND2  = (N * 64 + TB - 1) / TB;
    int nb_EW   = (E + 7) / 8;        // warp per edge, 8 warps/block

    // normalization
    k_init <<<nb_N, TB>>>(N);
    k_deg  <<<nb_E, TB>>>(dst, E);
    k_rsqrt<<<nb_N, TB>>>(N);

    // layer 1
    {
        dim3 grid(2, (N + 63) / 64);
        k_gemm<1><<<grid, TB>>>(x, W1, N);
    }
    k_self<1><<<nb_ND1, TB>>>(N * 128);
    k_edge<1><<<nb_EW, TB>>>(src, dst, E);
    k_brelu1 <<<nb_ND1, TB>>>(b1, N * 128);

    // layer 2
    {
        dim3 grid(1, (N + 63) / 64);
        k_gemm<2><<<grid, TB>>>(x /*unused*/, W2, N);
    }
    k_self<2><<<nb_ND2, TB>>>(N * 64);
    k_edge<2><<<nb_EW, TB>>>(src, dst, E);

    // pooling
    k_cnt  <<<nb_N, TB>>>(batch, N);
    k_pool <<<nb_ND2, TB>>>(batch, b2, N * 64);
    k_final<<<(NG * 64 + TB - 1) / TB, TB>>>(out);
}

// round 3
// speedup vs baseline: 1.2692x; 1.2692x over previous
#include <cuda_runtime.h>
#include <cuda_bf16.h>

#define NN 100000
#define NG 64

// ---------------- scratch (device globals; no allocation allowed) ----------
__device__ float g_dinv[NN];
__device__ float g_h1  [(size_t)NN * 128];
__device__ float g_agg1[(size_t)NN * 128];
__device__ float g_h2  [(size_t)NN * 64];
__device__ float g_agg2[(size_t)NN * 64];
__device__ float g_gsum[NG * 64];
__device__ float g_gcnt[NG];

__device__ __forceinline__ void red_add_v4(float* p, float4 v) {
    asm volatile("red.global.add.v4.f32 [%0], {%1, %2, %3, %4};"
                 :: "l"(p), "f"(v.x), "f"(v.y), "f"(v.z), "f"(v.w)
                 : "memory");
}

// ---------------- init: deg accumulator = 1 (self loop), zero pool bufs ----
__global__ void k_init(int n) {
    int i = blockIdx.x * blockDim.x + threadIdx.x;
    if (i < n)       g_dinv[i] = 1.0f;
    if (i < NG * 64) g_gsum[i] = 0.0f;
    if (i < NG)      g_gcnt[i] = 0.0f;
}

// ---------------- degree over dst -----------------------------------------
__global__ void k_deg(const int* __restrict__ dst, int E) {
    int e = blockIdx.x * blockDim.x + threadIdx.x;
    if (e < E) atomicAdd(&g_dinv[dst[e]], 1.0f);
}

__global__ void k_rsqrt(int n) {
    int i = blockIdx.x * blockDim.x + threadIdx.x;
    if (i < n) g_dinv[i] = rsqrtf(g_dinv[i]);
}

// ---------------- tiled fp32 GEMM: C[M,N] = A[M,K] @ B[K,N] ----------------
template <int LAYER>
__global__ void k_gemm(const float* __restrict__ Ain,
                       const float* __restrict__ B, int M) {
    constexpr int N = (LAYER == 1) ? 128 : 64;
    constexpr int K = 128;
    const float* __restrict__ A = (LAYER == 1) ? Ain : g_h1;
    float* __restrict__       C = (LAYER == 1) ? g_h1 : g_h2;

    __shared__ __align__(16) float As[16][64];   // [k][m] (transposed)
    __shared__ __align__(16) float Bs[16][64];   // [k][n]

    const int tid = threadIdx.x;          // 256 threads
    const int tx  = tid & 15;             // 0..15  -> 4 cols each
    const int ty  = tid >> 4;             // 0..15  -> 4 rows each
    const int mbase = blockIdx.y * 64;
    const int nbase = blockIdx.x * 64;

    const int ar = tid >> 2;              // 0..63 tile row
    const int ak = (tid & 3) << 2;        // 0,4,8,12
    const int br = tid >> 4;              // 0..15 tile k-row
    const int bn = (tid & 15) << 2;       // 0..60

    float acc[4][4];
#pragma unroll
    for (int i = 0; i < 4; i++)
#pragma unroll
        for (int j = 0; j < 4; j++) acc[i][j] = 0.0f;

    for (int k0 = 0; k0 < K; k0 += 16) {
        float4 av = make_float4(0.f, 0.f, 0.f, 0.f);
        if (mbase + ar < M)
            av = *reinterpret_cast<const float4*>(
                A + (size_t)(mbase + ar) * K + k0 + ak);
        As[ak + 0][ar] = av.x;
        As[ak + 1][ar] = av.y;
        As[ak + 2][ar] = av.z;
        As[ak + 3][ar] = av.w;

        float4 bv = *reinterpret_cast<const float4*>(
            B + (size_t)(k0 + br) * N + nbase + bn);
        *reinterpret_cast<float4*>(&Bs[br][bn]) = bv;

        __syncthreads();
#pragma unroll
        for (int kk = 0; kk < 16; kk++) {
            float4 a = *reinterpret_cast<const float4*>(&As[kk][ty * 4]);
            float4 b = *reinterpret_cast<const float4*>(&Bs[kk][tx * 4]);
            acc[0][0] += a.x * b.x; acc[0][1] += a.x * b.y; acc[0][2] += a.x * b.z; acc[0][3] += a.x * b.w;
            acc[1][0] += a.y * b.x; acc[1][1] += a.y * b.y; acc[1][2] += a.y * b.z; acc[1][3] += a.y * b.w;
            acc[2][0] += a.z * b.x; acc[2][1] += a.z * b.y; acc[2][2] += a.z * b.z; acc[2][3] += a.z * b.w;
            acc[3][0] += a.w * b.x; acc[3][1] += a.w * b.y; acc[3][2] += a.w * b.z; acc[3][3] += a.w * b.w;
        }
        __syncthreads();
    }

#pragma unroll
    for (int i = 0; i < 4; i++) {
        int m = mbase + ty * 4 + i;
        if (m < M) {
            float4 v = make_float4(acc[i][0], acc[i][1], acc[i][2], acc[i][3]);
            *reinterpret_cast<float4*>(C + (size_t)m * N + nbase + tx * 4) = v;
        }
    }
}

// ---------------- self-loop term: agg = dinv^2 * h (vectorized) ------------
template <int LAYER>
__global__ void k_self(int n4) {   // n4 = N * D / 4
    constexpr int D4 = ((LAYER == 1) ? 128 : 64) / 4;
    const float4* __restrict__ h   = (const float4*)((LAYER == 1) ? g_h1 : g_h2);
    float4* __restrict__       agg = (float4*)((LAYER == 1) ? g_agg1 : g_agg2);
    int i = blockIdx.x * blockDim.x + threadIdx.x;
    if (i < n4) {
        float di = g_dinv[i / D4];
        float s = di * di;
        float4 v = h[i];
        v.x *= s; v.y *= s; v.z *= s; v.w *= s;
        agg[i] = v;
    }
}

// ---------------- edge scatter L1 (D=128): warp/edge, float4 lanes ---------
__global__ void k_edge1(const int* __restrict__ src,
                        const int* __restrict__ dst, int E) {
    int w = (blockIdx.x * blockDim.x + threadIdx.x) >> 5;
    if (w >= E) return;
    int lane = threadIdx.x & 31;
    int s = __ldg(src + w);
    int d = __ldg(dst + w);
    float nw = g_dinv[s] * g_dinv[d];
    const float4* hs = (const float4*)(g_h1 + (size_t)s * 128);
    float*        ad = g_agg1 + (size_t)d * 128;
    float4 v = __ldg(hs + lane);
    v.x *= nw; v.y *= nw; v.z *= nw; v.w *= nw;
    red_add_v4(ad + lane * 4, v);
}

// ---------------- edge scatter L2 (D=64): 2 edges/warp, float4 lanes -------
__global__ void k_edge2(const int* __restrict__ src,
                        const int* __restrict__ dst, int E) {
    int half = (blockIdx.x * blockDim.x + threadIdx.x) >> 4;  // 16 lanes/edge
    if (half >= E) return;
    int l16 = threadIdx.x & 15;
    int s = __ldg(src + half);
    int d = __ldg(dst + half);
    float nw = g_dinv[s] * g_dinv[d];
    const float4* hs = (const float4*)(g_h2 + (size_t)s * 64);
    float*        ad = g_agg2 + (size_t)d * 64;
    float4 v = __ldg(hs + l16);
    v.x *= nw; v.y *= nw; v.z *= nw; v.w *= nw;
    red_add_v4(ad + l16 * 4, v);
}

// ---------------- layer-1 bias + relu (into g_h1 for reuse) ----------------
__global__ void k_brelu1(const float* __restrict__ b1, int n4) {
    int i = blockIdx.x * blockDim.x + threadIdx.x;
    if (i < n4) {
        float4 v = ((const float4*)g_agg1)[i];
        int f = (i & 31) * 4;
        v.x = fmaxf(v.x + __ldg(b1 + f + 0), 0.0f);
        v.y = fmaxf(v.y + __ldg(b1 + f + 1), 0.0f);
        v.z = fmaxf(v.z + __ldg(b1 + f + 2), 0.0f);
        v.w = fmaxf(v.w + __ldg(b1 + f + 3), 0.0f);
        ((float4*)g_h1)[i] = v;
    }
}

// ---------------- per-graph node counts ------------------------------------
__global__ void k_cnt(const int* __restrict__ batch, int n) {
    int i = blockIdx.x * blockDim.x + threadIdx.x;
    if (i < n) atomicAdd(&g_gcnt[batch[i]], 1.0f);
}

// ---------------- layer-2 bias + relu + pooled sums ------------------------
__global__ void k_pool(const int* __restrict__ batch,
                       const float* __restrict__ b2, int n4) {
    int i = blockIdx.x * blockDim.x + threadIdx.x;
    if (i < n4) {
        int node = i >> 4;          // 16 float4 per node
        int f    = (i & 15) * 4;
        float4 v = ((const float4*)g_agg2)[i];
        v.x = fmaxf(v.x + __ldg(b2 + f + 0), 0.0f);
        v.y = fmaxf(v.y + __ldg(b2 + f + 1), 0.0f);
        v.z = fmaxf(v.z + __ldg(b2 + f + 2), 0.0f);
        v.w = fmaxf(v.w + __ldg(b2 + f + 3), 0.0f);
        int g = __ldg(batch + node);
        red_add_v4(&g_gsum[(g << 6) + f], v);
    }
}

// ---------------- mean -----------------------------------------------------
__global__ void k_final(float* __restrict__ out) {
    int i = blockIdx.x * blockDim.x + threadIdx.x;
    if (i < NG * 64) out[i] = g_gsum[i] / fmaxf(g_gcnt[i >> 6], 1.0f);
}

// ===========================================================================
extern "C" void kernel_launch(void* const* d_in, const int* in_sizes, int n_in,
                              void* d_out, int out_size) {
    const float* x     = (const float*)d_in[0];
    const int*   ei    = (const int*)d_in[1];
    const int*   batch = (const int*)d_in[2];
    const float* W1    = (const float*)d_in[3];
    const float* b1    = (const float*)d_in[4];
    const float* W2    = (const float*)d_in[5];
    const float* b2    = (const float*)d_in[6];
    float*       out   = (float*)d_out;

    const int N = in_sizes[2];        // 100000 nodes
    const int E = in_sizes[1] / 2;    // 1600000 edges
    const int* src = ei;
    const int* dst = ei + E;

    const int TB = 256;
    int nb_N   = (N + TB - 1) / TB;
    int nb_E   = (E + TB - 1) / TB;
    int n4_1   = N * 128 / 4;
    int n4_2   = N * 64 / 4;
    int nb_41  = (n4_1 + TB - 1) / TB;
    int nb_42  = (n4_2 + TB - 1) / TB;
    int nb_E1  = (E + 7) / 8;          // warp/edge, 8 warps per block
    int nb_E2  = (E + 15) / 16;        // halfwarp/edge

    // normalization
    k_init <<<nb_N, TB>>>(N);
    k_deg  <<<nb_E, TB>>>(dst, E);
    k_rsqrt<<<nb_N, TB>>>(N);

    // layer 1
    {
        dim3 grid(2, (N + 63) / 64);
        k_gemm<1><<<grid, TB>>>(x, W1, N);
    }
    k_self<1><<<nb_41, TB>>>(n4_1);
    k_edge1  <<<nb_E1, TB>>>(src, dst, E);
    k_brelu1 <<<nb_41, TB>>>(b1, n4_1);

    // layer 2
    {
        dim3 grid(1, (N + 63) / 64);
        k_gemm<2><<<grid, TB>>>(x /*unused*/, W2, N);
    }
    k_self<2><<<nb_42, TB>>>(n4_2);
    k_edge2  <<<nb_E2, TB>>>(src, dst, E);

    // pooling
    k_cnt  <<<nb_N, TB>>>(batch, N);
    k_pool <<<nb_42, TB>>>(batch, b2, n4_2);
    k_final<<<(NG * 64 + TB - 1) / TB, TB>>>(out);
}

// round 5
// speedup vs baseline: 2.0000x; 1.5758x over previous
#include <cuda_runtime.h>
#include <cuda_bf16.h>

#define NN 100000
#define NE 1600000
#define NG 64

// ---------------- scratch (device globals) ---------------------------------
__device__ float g_dinv[NN];
__device__ int   g_deg[NN];
__device__ int   g_rowptr[NN];
__device__ int   g_cursor[NN];
__device__ int   g_bsum[128];
__device__ int   g_csr[NE];
__device__ float g_h1p[(size_t)NN * 128];   // dinv * (x W1)
__device__ float g_h1 [(size_t)NN * 128];   // post agg+relu (gemm2 input)
__device__ float g_h2p[(size_t)NN * 64];    // dinv * (h1 W2)
__device__ float g_gsum[NG * 64];
__device__ float g_gcnt[NG];

__device__ __forceinline__ void red_add_v4(float* p, float4 v) {
    asm volatile("red.global.add.v4.f32 [%0], {%1, %2, %3, %4};"
                 :: "l"(p), "f"(v.x), "f"(v.y), "f"(v.z), "f"(v.w)
                 : "memory");
}

// ---------------- init ------------------------------------------------------
__global__ void k_init(int n) {
    int i = blockIdx.x * blockDim.x + threadIdx.x;
    if (i < n)       g_deg[i] = 0;
    if (i < NG * 64) g_gsum[i] = 0.0f;
    if (i < NG)      g_gcnt[i] = 0.0f;
}

// ---------------- degree histogram over dst --------------------------------
__global__ void k_hist(const int* __restrict__ dst, int E) {
    int e = blockIdx.x * blockDim.x + threadIdx.x;
    if (e < E) atomicAdd(&g_deg[dst[e]], 1);
}

// ---------------- scan step 1: per-block (1024) inclusive scan -------------
__global__ void k_scan1(int n) {
    __shared__ int sh[1024];
    int tid = threadIdx.x;
    int i = blockIdx.x * 1024 + tid;
    int v = (i < n) ? g_deg[i] : 0;
    sh[tid] = v;
    __syncthreads();
#pragma unroll
    for (int off = 1; off < 1024; off <<= 1) {
        int t = (tid >= off) ? sh[tid - off] : 0;
        __syncthreads();
        sh[tid] += t;
        __syncthreads();
    }
    if (i < n) g_rowptr[i] = sh[tid] - v;          // exclusive
    if (tid == 1023) g_bsum[blockIdx.x] = sh[1023];
}

// ---------------- scan step 2: scan of block sums (~98 entries) ------------
__global__ void k_scan2(int nb) {
    if (threadIdx.x == 0 && blockIdx.x == 0) {
        int acc = 0;
        for (int b = 0; b < nb; b++) { int t = g_bsum[b]; g_bsum[b] = acc; acc += t; }
    }
}

// ---------------- scan step 3: add block offsets, copy cursor, dinv --------
__global__ void k_scan3(int n) {
    int i = blockIdx.x * blockDim.x + threadIdx.x;
    if (i < n) {
        int r = g_rowptr[i] + g_bsum[i >> 10];
        g_rowptr[i] = r;
        g_cursor[i] = r;
        g_dinv[i]   = rsqrtf((float)g_deg[i] + 1.0f);   // +1 self loop
    }
}

// ---------------- CSR scatter ----------------------------------------------
__global__ void k_scatter(const int* __restrict__ src,
                          const int* __restrict__ dst, int E) {
    int e = blockIdx.x * blockDim.x + threadIdx.x;
    if (e < E) {
        int pos = atomicAdd(&g_cursor[dst[e]], 1);
        g_csr[pos] = src[e];
    }
}

// ---------------- GEMM: C[m] = dinv[m] * (A[m] @ W), 128xBN tile -----------
// LAYER 1: A = x (arg), C = g_h1p, BN = 128.
// LAYER 2: A = g_h1,    C = g_h2p, BN = 64.
// 256 threads, per-thread 8 rows x (BN/16) cols.
template <int LAYER>
__global__ void k_gemm(const float* __restrict__ Ain,
                       const float* __restrict__ W, int M) {
    constexpr int BN = (LAYER == 1) ? 128 : 64;
    constexpr int K  = 128;
    constexpr int TN = BN / 16;                 // 8 or 4
    const float* __restrict__ A = (LAYER == 1) ? Ain : g_h1;
    float* __restrict__       C = (LAYER == 1) ? g_h1p : g_h2p;

    __shared__ __align__(16) float As[16][128];
    __shared__ __align__(16) float Bs[16][BN];

    const int t     = threadIdx.x;
    const int mbase = blockIdx.x * 128;
    const int ty    = t >> 4;                   // 0..15 -> rows ty*8..+7
    const int tx    = t & 15;                   // 0..15 -> cols tx*TN..+TN-1

    float acc[8][TN];
#pragma unroll
    for (int i = 0; i < 8; i++)
#pragma unroll
        for (int j = 0; j < TN; j++) acc[i][j] = 0.0f;

    for (int k0 = 0; k0 < K; k0 += 16) {
        // A tile: 128 rows x 16 k = 512 float4, 2 per thread, transposed
#pragma unroll
        for (int j = 0; j < 2; j++) {
            int idx = t + j * 256;
            int row = idx >> 2;
            int kq  = (idx & 3) << 2;
            float4 av = make_float4(0.f, 0.f, 0.f, 0.f);
            if (mbase + row < M)
                av = *reinterpret_cast<const float4*>(
                    A + (size_t)(mbase + row) * K + k0 + kq);
            As[kq + 0][row] = av.x;
            As[kq + 1][row] = av.y;
            As[kq + 2][row] = av.z;
            As[kq + 3][row] = av.w;
        }
        // B tile: 16 x BN = 4*BN float4
        constexpr int B4 = 16 * BN / 4;
#pragma unroll
        for (int j = 0; j < (B4 + 255) / 256; j++) {
            int idx = t + j * 256;
            if (idx < B4) {
                int brow = idx / (BN / 4);
                int bcol = (idx % (BN / 4)) << 2;
                *reinterpret_cast<float4*>(&Bs[brow][bcol]) =
                    *reinterpret_cast<const float4*>(W + (size_t)(k0 + brow) * BN + bcol);
            }
        }
        __syncthreads();
#pragma unroll
        for (int kk = 0; kk < 16; kk++) {
            float a[8], b[TN];
            *reinterpret_cast<float4*>(&a[0]) = *reinterpret_cast<const float4*>(&As[kk][ty * 8 + 0]);
            *reinterpret_cast<float4*>(&a[4]) = *reinterpret_cast<const float4*>(&As[kk][ty * 8 + 4]);
            *reinterpret_cast<float4*>(&b[0]) = *reinterpret_cast<const float4*>(&Bs[kk][tx * TN + 0]);
            if (TN == 8)
                *reinterpret_cast<float4*>(&b[4]) = *reinterpret_cast<const float4*>(&Bs[kk][tx * TN + 4]);
#pragma unroll
            for (int i = 0; i < 8; i++)
#pragma unroll
                for (int j = 0; j < TN; j++) acc[i][j] += a[i] * b[j];
        }
        __syncthreads();
    }

#pragma unroll
    for (int i = 0; i < 8; i++) {
        int m = mbase + ty * 8 + i;
        if (m < M) {
            float s = g_dinv[m];
#pragma unroll
            for (int j = 0; j < TN; j += 4) {
                float4 v = make_float4(s * acc[i][j], s * acc[i][j + 1],
                                       s * acc[i][j + 2], s * acc[i][j + 3]);
                *reinterpret_cast<float4*>(C + (size_t)m * BN + tx * TN + j) = v;
            }
        }
    }
}

// ---------------- agg layer 1 (D=128): warp per node -----------------------
__global__ void k_agg1(const float* __restrict__ b1, int N) {
    int w = (blockIdx.x * blockDim.x + threadIdx.x) >> 5;
    if (w >= N) return;
    int lane = threadIdx.x & 31;
    const float4* H = (const float4*)g_h1p;

    int start = g_rowptr[w];
    int cnt   = g_deg[w];
    float4 acc = __ldg(H + (size_t)w * 32 + lane);   // self term
    int j = 0;
    for (; j + 4 <= cnt; j += 4) {
        int s0 = __ldg(g_csr + start + j + 0);
        int s1 = __ldg(g_csr + start + j + 1);
        int s2 = __ldg(g_csr + start + j + 2);
        int s3 = __ldg(g_csr + start + j + 3);
        float4 v0 = __ldg(H + (size_t)s0 * 32 + lane);
        float4 v1 = __ldg(H + (size_t)s1 * 32 + lane);
        float4 v2 = __ldg(H + (size_t)s2 * 32 + lane);
        float4 v3 = __ldg(H + (size_t)s3 * 32 + lane);
        acc.x += v0.x + v1.x + v2.x + v3.x;
        acc.y += v0.y + v1.y + v2.y + v3.y;
        acc.z += v0.z + v1.z + v2.z + v3.z;
        acc.w += v0.w + v1.w + v2.w + v3.w;
    }
    for (; j < cnt; j++) {
        int s = __ldg(g_csr + start + j);
        float4 v = __ldg(H + (size_t)s * 32 + lane);
        acc.x += v.x; acc.y += v.y; acc.z += v.z; acc.w += v.w;
    }
    float di = g_dinv[w];
    float4 bb = __ldg((const float4*)b1 + lane);
    acc.x = fmaxf(di * acc.x + bb.x, 0.0f);
    acc.y = fmaxf(di * acc.y + bb.y, 0.0f);
    acc.z = fmaxf(di * acc.z + bb.z, 0.0f);
    acc.w = fmaxf(di * acc.w + bb.w, 0.0f);
    ((float4*)g_h1)[(size_t)w * 32 + lane] = acc;
}

// ---------------- agg layer 2 (D=64) + pool: 16 threads per node -----------
__global__ void k_agg2(const int* __restrict__ batch,
                       const float* __restrict__ b2, int N) {
    int idx = blockIdx.x * blockDim.x + threadIdx.x;
    int node = idx >> 4;
    if (node >= N) return;
    int f4 = idx & 15;
    const float4* H = (const float4*)g_h2p;

    int start = g_rowptr[node];
    int cnt   = g_deg[node];
    float4 acc = __ldg(H + (size_t)node * 16 + f4);  // self term
    int j = 0;
    for (; j + 4 <= cnt; j += 4) {
        int s0 = __ldg(g_csr + start + j + 0);
        int s1 = __ldg(g_csr + start + j + 1);
        int s2 = __ldg(g_csr + start + j + 2);
        int s3 = __ldg(g_csr + start + j + 3);
        float4 v0 = __ldg(H + (size_t)s0 * 16 + f4);
        float4 v1 = __ldg(H + (size_t)s1 * 16 + f4);
        float4 v2 = __ldg(H + (size_t)s2 * 16 + f4);
        float4 v3 = __ldg(H + (size_t)s3 * 16 + f4);
        acc.x += v0.x + v1.x + v2.x + v3.x;
        acc.y += v0.y + v1.y + v2.y + v3.y;
        acc.z += v0.z + v1.z + v2.z + v3.z;
        acc.w += v0.w + v1.w + v2.w + v3.w;
    }
    for (; j < cnt; j++) {
        int s = __ldg(g_csr + start + j);
        float4 v = __ldg(H + (size_t)s * 16 + f4);
        acc.x += v.x; acc.y += v.y; acc.z += v.z; acc.w += v.w;
    }
    float di = g_dinv[node];
    float4 bb = __ldg((const float4*)b2 + f4);
    acc.x = fmaxf(di * acc.x + bb.x, 0.0f);
    acc.y = fmaxf(di * acc.y + bb.y, 0.0f);
    acc.z = fmaxf(di * acc.z + bb.z, 0.0f);
    acc.w = fmaxf(di * acc.w + bb.w, 0.0f);

    int g = __ldg(batch + node);
    red_add_v4(&g_gsum[(g << 6) + (f4 << 2)], acc);
}

// ---------------- per-graph node counts ------------------------------------
__global__ void k_cnt(const int* __restrict__ batch, int n) {
    int i = blockIdx.x * blockDim.x + threadIdx.x;
    if (i < n) atomicAdd(&g_gcnt[batch[i]], 1.0f);
}

// ---------------- mean -----------------------------------------------------
__global__ void k_final(float* __restrict__ out) {
    int i = blockIdx.x * blockDim.x + threadIdx.x;
    if (i < NG * 64) out[i] = g_gsum[i] / fmaxf(g_gcnt[i >> 6], 1.0f);
}

// ===========================================================================
extern "C" void kernel_launch(void* const* d_in, const int* in_sizes, int n_in,
                              void* d_out, int out_size) {
    const float* x     = (const float*)d_in[0];
    const int*   ei    = (const int*)d_in[1];
    const int*   batch = (const int*)d_in[2];
    const float* W1    = (const float*)d_in[3];
    const float* b1    = (const float*)d_in[4];
    const float* W2    = (const float*)d_in[5];
    const float* b2    = (const float*)d_in[6];
    float*       out   = (float*)d_out;

    const int N = in_sizes[2];        // 100000
    const int E = in_sizes[1] / 2;    // 1600000
    const int* src = ei;
    const int* dst = ei + E;

    const int TB = 256;
    int nb_N  = (N + TB - 1) / TB;
    int nb_E  = (E + TB - 1) / TB;
    int nb_sc = (N + 1023) / 1024;    // scan blocks

    // graph prep: degree, rowptr, csr, dinv
    k_init   <<<nb_N, TB>>>(N);
    k_hist   <<<nb_E, TB>>>(dst, E);
    k_scan1  <<<nb_sc, 1024>>>(N);
    k_scan2  <<<1, 32>>>(nb_sc);
    k_scan3  <<<nb_N, TB>>>(N);
    k_scatter<<<nb_E, TB>>>(src, dst, E);

    // layer 1
    k_gemm<1><<<(N + 127) / 128, TB>>>(x, W1, N);
    k_agg1   <<<(N * 32 + TB - 1) / TB, TB>>>(b1, N);

    // layer 2 + pool
    k_gemm<2><<<(N + 127) / 128, TB>>>(nullptr, W2, N);
    k_cnt    <<<nb_N, TB>>>(batch, N);
    k_agg2   <<<(N * 16 + TB - 1) / TB, TB>>>(batch, b2, N);

    k_final<<<(NG * 64 + TB - 1) / TB, TB>>>(out);
}

// round 6
// speedup vs baseline: 2.1877x; 1.0938x over previous
#include <cuda_runtime.h>
#include <cuda_bf16.h>
#include <mma.h>
using namespace nvcuda;

#define NN 100000
#define NE 1600000
#define NG 64

// ---------------- scratch (device globals) ---------------------------------
__device__ float g_dinv[NN];
__device__ int   g_deg[NN];
__device__ int   g_rowptr[NN];
__device__ int   g_cursor[NN];
__device__ int   g_bsum[128];
__device__ int   g_csr[NE];
__device__ float g_h1p[(size_t)NN * 128];   // dinv * (x W1)
__device__ float g_h1 [(size_t)NN * 128];   // post agg+relu (gemm2 input)
__device__ float g_h2p[(size_t)NN * 64];    // dinv * (h1 W2)
__device__ float g_gsum[NG * 64];
__device__ float g_gcnt[NG];

__device__ __forceinline__ void red_add_v4(float* p, float4 v) {
    asm volatile("red.global.add.v4.f32 [%0], {%1, %2, %3, %4};"
                 :: "l"(p), "f"(v.x), "f"(v.y), "f"(v.z), "f"(v.w)
                 : "memory");
}

// ---------------- init ------------------------------------------------------
__global__ void k_init(int n) {
    int i = blockIdx.x * blockDim.x + threadIdx.x;
    if (i < n)       g_deg[i] = 0;
    if (i < NG * 64) g_gsum[i] = 0.0f;
    if (i < NG)      g_gcnt[i] = 0.0f;
}

// ---------------- degree histogram over dst --------------------------------
__global__ void k_hist(const int* __restrict__ dst, int E) {
    int e = blockIdx.x * blockDim.x + threadIdx.x;
    if (e < E) atomicAdd(&g_deg[dst[e]], 1);
}

// ---------------- scan step 1: per-block (1024) scan -----------------------
__global__ void k_scan1(int n) {
    __shared__ int sh[1024];
    int tid = threadIdx.x;
    int i = blockIdx.x * 1024 + tid;
    int v = (i < n) ? g_deg[i] : 0;
    sh[tid] = v;
    __syncthreads();
#pragma unroll
    for (int off = 1; off < 1024; off <<= 1) {
        int t = (tid >= off) ? sh[tid - off] : 0;
        __syncthreads();
        sh[tid] += t;
        __syncthreads();
    }
    if (i < n) g_rowptr[i] = sh[tid] - v;          // exclusive
    if (tid == 1023) g_bsum[blockIdx.x] = sh[1023];
}

// ---------------- scan step 2: warp-shuffle scan of block sums -------------
__global__ void k_scan2(int nb) {
    int lane = threadIdx.x;   // 32 threads
    int carry = 0;
    for (int base = 0; base < nb; base += 32) {
        int idx = base + lane;
        int orig = (idx < nb) ? g_bsum[idx] : 0;
        int v = orig;
#pragma unroll
        for (int off = 1; off < 32; off <<= 1) {
            int u = __shfl_up_sync(0xFFFFFFFFu, v, off);
            if (lane >= off) v += u;
        }
        if (idx < nb) g_bsum[idx] = v - orig + carry;   // exclusive + carry
        carry += __shfl_sync(0xFFFFFFFFu, v, 31);
    }
}

// ---------------- scan step 3: add block offsets, copy cursor, dinv --------
__global__ void k_scan3(int n) {
    int i = blockIdx.x * blockDim.x + threadIdx.x;
    if (i < n) {
        int r = g_rowptr[i] + g_bsum[i >> 10];
        g_rowptr[i] = r;
        g_cursor[i] = r;
        g_dinv[i]   = rsqrtf((float)g_deg[i] + 1.0f);   // +1 self loop
    }
}

// ---------------- CSR scatter ----------------------------------------------
__global__ void k_scatter(const int* __restrict__ src,
                          const int* __restrict__ dst, int E) {
    int e = blockIdx.x * blockDim.x + threadIdx.x;
    if (e < E) {
        int pos = atomicAdd(&g_cursor[dst[e]], 1);
        g_csr[pos] = src[e];
    }
}

// ---------------- TF32 GEMM: C[m] = (dinv[m]*A[m]) @ W ---------------------
// LAYER 1: A = x (arg), C = g_h1p, BN = 128.  LAYER 2: A = g_h1, C = g_h2p, BN = 64.
// 256 threads = 8 warps; block tile 128 x BN; warp tile 32 x BN/2.
template <int LAYER>
__global__ void k_gemm(const float* __restrict__ Ain,
                       const float* __restrict__ W, int M) {
    constexpr int BN  = (LAYER == 1) ? 128 : 64;
    constexpr int K   = 128;
    constexpr int KC  = 32;
    constexpr int LDA = KC + 8;
    constexpr int LDB = BN + 8;
    constexpr int WN  = BN / 2;                 // warp tile N: 64 or 32
    constexpr int NF  = WN / 16;                // n-frags: 4 or 2
    const float* __restrict__ A = (LAYER == 1) ? Ain : g_h1;
    float* __restrict__       C = (LAYER == 1) ? g_h1p : g_h2p;

    __shared__ __align__(16) float As[128][LDA];
    __shared__ __align__(16) float Bs[KC][LDB];
    __shared__ __align__(16) float stage[8][16][17];

    const int t    = threadIdx.x;
    const int wid  = t >> 5;
    const int lane = t & 31;
    const int mbase = blockIdx.x * 128;
    const int wm = (wid >> 1) * 32;             // warp row offset
    const int wn = (wid & 1) * WN;              // warp col offset

    wmma::fragment<wmma::accumulator, 16, 16, 8, float> c[2][NF];
#pragma unroll
    for (int i = 0; i < 2; i++)
#pragma unroll
        for (int j = 0; j < NF; j++) wmma::fill_fragment(c[i][j], 0.0f);

    for (int k0 = 0; k0 < K; k0 += KC) {
        // A tile: 128 x 32 floats, dinv-scaled rows; 1024 float4, 4/thread
#pragma unroll
        for (int j = 0; j < 4; j++) {
            int idx = t + j * 256;
            int row = idx >> 3;
            int kq  = (idx & 7) << 2;
            float4 av = make_float4(0.f, 0.f, 0.f, 0.f);
            float  s  = 0.0f;
            if (mbase + row < M) {
                av = *reinterpret_cast<const float4*>(
                    A + (size_t)(mbase + row) * K + k0 + kq);
                s = g_dinv[mbase + row];
            }
            As[row][kq + 0] = s * av.x;
            As[row][kq + 1] = s * av.y;
            As[row][kq + 2] = s * av.z;
            As[row][kq + 3] = s * av.w;
        }
        // B tile: KC x BN floats; KC*BN/4 float4
        constexpr int B4   = KC * BN / 4;       // 1024 or 512
        constexpr int BIT  = B4 / 256;          // 4 or 2
#pragma unroll
        for (int j = 0; j < BIT; j++) {
            int idx = t + j * 256;
            int row = idx / (BN / 4);
            int col = (idx % (BN / 4)) << 2;
            float4 bv = *reinterpret_cast<const float4*>(
                W + (size_t)(k0 + row) * BN + col);
            Bs[row][col + 0] = bv.x;
            Bs[row][col + 1] = bv.y;
            Bs[row][col + 2] = bv.z;
            Bs[row][col + 3] = bv.w;
        }
        __syncthreads();

#pragma unroll
        for (int kk = 0; kk < KC; kk += 8) {
            wmma::fragment<wmma::matrix_a, 16, 16, 8, wmma::precision::tf32, wmma::row_major> a[2];
            wmma::fragment<wmma::matrix_b, 16, 16, 8, wmma::precision::tf32, wmma::row_major> b[NF];
#pragma unroll
            for (int i = 0; i < 2; i++) {
                wmma::load_matrix_sync(a[i], &As[wm + i * 16][kk], LDA);
#pragma unroll
                for (int e = 0; e < a[i].num_elements; e++)
                    a[i].x[e] = wmma::__float_to_tf32(a[i].x[e]);
            }
#pragma unroll
            for (int j = 0; j < NF; j++) {
                wmma::load_matrix_sync(b[j], &Bs[kk][wn + j * 16], LDB);
#pragma unroll
                for (int e = 0; e < b[j].num_elements; e++)
                    b[j].x[e] = wmma::__float_to_tf32(b[j].x[e]);
            }
#pragma unroll
            for (int i = 0; i < 2; i++)
#pragma unroll
                for (int j = 0; j < NF; j++)
                    wmma::mma_sync(c[i][j], a[i], b[j], c[i][j]);
        }
        __syncthreads();
    }

    // epilogue
    if (mbase + 128 <= M) {
#pragma unroll
        for (int i = 0; i < 2; i++)
#pragma unroll
            for (int j = 0; j < NF; j++)
                wmma::store_matrix_sync(
                    C + (size_t)(mbase + wm + i * 16) * BN + wn + j * 16,
                    c[i][j], BN, wmma::mem_row_major);
    } else {
        // tail block: stage each 16x16 frag in smem, guarded copy
#pragma unroll
        for (int i = 0; i < 2; i++)
#pragma unroll
            for (int j = 0; j < NF; j++) {
                wmma::store_matrix_sync(&stage[wid][0][0], c[i][j], 17,
                                        wmma::mem_row_major);
                __syncwarp();
#pragma unroll
                for (int r2 = 0; r2 < 8; r2++) {
                    int rr = (lane >> 4) + r2 * 2;       // 0..15
                    int cc = lane & 15;
                    int m = mbase + wm + i * 16 + rr;
                    if (m < M)
                        C[(size_t)m * BN + wn + j * 16 + cc] = stage[wid][rr][cc];
                }
                __syncwarp();
            }
    }
}

// ---------------- agg layer 1 (D=128): warp per node -----------------------
__global__ void k_agg1(const float* __restrict__ b1, int N) {
    int w = (blockIdx.x * blockDim.x + threadIdx.x) >> 5;
    if (w >= N) return;
    int lane = threadIdx.x & 31;
    const float4* H = (const float4*)g_h1p;

    int start = g_rowptr[w];
    int cnt   = g_deg[w];
    float4 acc = __ldg(H + (size_t)w * 32 + lane);   // self term
    int j = 0;
    for (; j + 4 <= cnt; j += 4) {
        int s0 = __ldg(g_csr + start + j + 0);
        int s1 = __ldg(g_csr + start + j + 1);
        int s2 = __ldg(g_csr + start + j + 2);
        int s3 = __ldg(g_csr + start + j + 3);
        float4 v0 = __ldg(H + (size_t)s0 * 32 + lane);
        float4 v1 = __ldg(H + (size_t)s1 * 32 + lane);
        float4 v2 = __ldg(H + (size_t)s2 * 32 + lane);
        float4 v3 = __ldg(H + (size_t)s3 * 32 + lane);
        acc.x += v0.x + v1.x + v2.x + v3.x;
        acc.y += v0.y + v1.y + v2.y + v3.y;
        acc.z += v0.z + v1.z + v2.z + v3.z;
        acc.w += v0.w + v1.w + v2.w + v3.w;
    }
    for (; j < cnt; j++) {
        int s = __ldg(g_csr + start + j);
        float4 v = __ldg(H + (size_t)s * 32 + lane);
        acc.x += v.x; acc.y += v.y; acc.z += v.z; acc.w += v.w;
    }
    float di = g_dinv[w];
    float4 bb = __ldg((const float4*)b1 + lane);
    acc.x = fmaxf(di * acc.x + bb.x, 0.0f);
    acc.y = fmaxf(di * acc.y + bb.y, 0.0f);
    acc.z = fmaxf(di * acc.z + bb.z, 0.0f);
    acc.w = fmaxf(di * acc.w + bb.w, 0.0f);
    ((float4*)g_h1)[(size_t)w * 32 + lane] = acc;
}

// ---------------- agg layer 2 (D=64) + pool: 16 threads per node -----------
__global__ void k_agg2(const int* __restrict__ batch,
                       const float* __restrict__ b2, int N) {
    int idx = blockIdx.x * blockDim.x + threadIdx.x;
    int node = idx >> 4;
    if (node >= N) return;
    int f4 = idx & 15;
    const float4* H = (const float4*)g_h2p;

    int start = g_rowptr[node];
    int cnt   = g_deg[node];
    float4 acc = __ldg(H + (size_t)node * 16 + f4);  // self term
    int j = 0;
    for (; j + 4 <= cnt; j += 4) {
        int s0 = __ldg(g_csr + start + j + 0);
        int s1 = __ldg(g_csr + start + j + 1);
        int s2 = __ldg(g_csr + start + j + 2);
        int s3 = __ldg(g_csr + start + j + 3);
        float4 v0 = __ldg(H + (size_t)s0 * 16 + f4);
        float4 v1 = __ldg(H + (size_t)s1 * 16 + f4);
        float4 v2 = __ldg(H + (size_t)s2 * 16 + f4);
        float4 v3 = __ldg(H + (size_t)s3 * 16 + f4);
        acc.x += v0.x + v1.x + v2.x + v3.x;
        acc.y += v0.y + v1.y + v2.y + v3.y;
        acc.z += v0.z + v1.z + v2.z + v3.z;
        acc.w += v0.w + v1.w + v2.w + v3.w;
    }
    for (; j < cnt; j++) {
        int s = __ldg(g_csr + start + j);
        float4 v = __ldg(H + (size_t)s * 16 + f4);
        acc.x += v.x; acc.y += v.y; acc.z += v.z; acc.w += v.w;
    }
    float di = g_dinv[node];
    float4 bb = __ldg((const float4*)b2 + f4);
    acc.x = fmaxf(di * acc.x + bb.x, 0.0f);
    acc.y = fmaxf(di * acc.y + bb.y, 0.0f);
    acc.z = fmaxf(di * acc.z + bb.z, 0.0f);
    acc.w = fmaxf(di * acc.w + bb.w, 0.0f);

    int g = __ldg(batch + node);
    red_add_v4(&g_gsum[(g << 6) + (f4 << 2)], acc);
}

// ---------------- per-graph node counts ------------------------------------
__global__ void k_cnt(const int* __restrict__ batch, int n) {
    int i = blockIdx.x * blockDim.x + threadIdx.x;
    if (i < n) atomicAdd(&g_gcnt[batch[i]], 1.0f);
}

// ---------------- mean -----------------------------------------------------
__global__ void k_final(float* __restrict__ out) {
    int i = blockIdx.x * blockDim.x + threadIdx.x;
    if (i < NG * 64) out[i] = g_gsum[i] / fmaxf(g_gcnt[i >> 6], 1.0f);
}

// ===========================================================================
extern "C" void kernel_launch(void* const* d_in, const int* in_sizes, int n_in,
                              void* d_out, int out_size) {
    const float* x     = (const float*)d_in[0];
    const int*   ei    = (const int*)d_in[1];
    const int*   batch = (const int*)d_in[2];
    const float* W1    = (const float*)d_in[3];
    const float* b1    = (const float*)d_in[4];
    const float* W2    = (const float*)d_in[5];
    const float* b2    = (const float*)d_in[6];
    float*       out   = (float*)d_out;

    const int N = in_sizes[2];        // 100000
    const int E = in_sizes[1] / 2;    // 1600000
    const int* src = ei;
    const int* dst = ei + E;

    const int TB = 256;
    int nb_N  = (N + TB - 1) / TB;
    int nb_E  = (E + TB - 1) / TB;
    int nb_sc = (N + 1023) / 1024;    // scan blocks

    // graph prep: degree, rowptr, csr, dinv
    k_init   <<<nb_N, TB>>>(N);
    k_hist   <<<nb_E, TB>>>(dst, E);
    k_scan1  <<<nb_sc, 1024>>>(N);
    k_scan2  <<<1, 32>>>(nb_sc);
    k_scan3  <<<nb_N, TB>>>(N);
    k_scatter<<<nb_E, TB>>>(src, dst, E);

    // layer 1
    k_gemm<1><<<(N + 127) / 128, TB>>>(x, W1, N);
    k_agg1   <<<(N * 32 + TB - 1) / TB, TB>>>(b1, N);

    // layer 2 + pool
    k_gemm<2><<<(N + 127) / 128, TB>>>(nullptr, W2, N);
    k_cnt    <<<nb_N, TB>>>(batch, N);
    k_agg2   <<<(N * 16 + TB - 1) / TB, TB>>>(batch, b2, N);

    k_final<<<(NG * 64 + TB - 1) / TB, TB>>>(out);
}